// round 12
// baseline (speedup 1.0000x reference)
#include <cuda_runtime.h>
#include <cuda_fp16.h>
#include <stdint.h>
#include <math.h>

#define N_NODES 50000
#define N_EDGES 500000
#define DIM     128
#define N_REL   51
#define KDIM    1664   // 13*128
#define BK      32
#define NKT     (KDIM / BK)   // 52
#define NSTG    4
#define TILEA   5120           // 64 rows * 80B
#define TILEBB  10240          // 128 rows * 80B
#define NGRP    6250           // N_NODES / 8

// k_prep block-range offsets
#define PB_FILL  0
#define PB_ZERO  1954
#define PB_CVTX  2150
#define PB_CVTW  8400
#define PB_CVTR  9232
#define PB_TOT   9334

// ---------------- scratch (device globals; no allocation allowed) ----------
__device__ int    g_deg[N_NODES];
__device__ int    g_off[N_NODES + 1];
__device__ int    g_fill[N_NODES];
__device__ int    g_epk[N_EDGES];     // packed src | (type<<17)
__device__ float  g_ew[N_EDGES];
__device__ float  g_scaleS[N_NODES];
__device__ float  g_x[N_NODES * DIM];
__device__ __half g_Ah[(size_t)NKT * N_NODES * 32];  // chunk-major half A matrix
__device__ __half g_Wth[4 * DIM * KDIM];             // transposed half weights [l][n][k]
__device__ __half g_relh[4 * N_REL * DIM];           // half rel weights

// ---------------- preprocessing -------------------------------------------
__global__ void k_hist(const int* __restrict__ edst) {
    int e = blockIdx.x * blockDim.x + threadIdx.x;
    if (e < N_EDGES) atomicAdd(&g_deg[edst[e]], 1);
}

// single block, 1024 threads; 8 elements per thread per chunk.
__global__ void k_scan() {
    __shared__ int   wsum[32];
    __shared__ int   carry_sh;
    __shared__ float fred[32];
    __shared__ float ssum_sh;
    int tid  = threadIdx.x;
    int lane = tid & 31, wid = tid >> 5;
    if (tid == 0) carry_sh = 0;
    __syncthreads();

    float ls = 0.0f;
#pragma unroll 1
    for (int c = 0; c < 7; c++) {
        int g = c * 1024 + tid;
        int v[8];
        int tsum = 0;
        if (g < NGRP) {
            int4 a = *reinterpret_cast<const int4*>(g_deg + g * 8);
            int4 b = *reinterpret_cast<const int4*>(g_deg + g * 8 + 4);
            v[0] = a.x; v[1] = a.y; v[2] = a.z; v[3] = a.w;
            v[4] = b.x; v[5] = b.y; v[6] = b.z; v[7] = b.w;
#pragma unroll
            for (int j = 0; j < 8; j++) tsum += v[j];
        } else {
#pragma unroll
            for (int j = 0; j < 8; j++) v[j] = 0;
        }
        int x = tsum;
#pragma unroll
        for (int off = 1; off < 32; off <<= 1) {
            int y = __shfl_up_sync(0xffffffffu, x, off);
            if (lane >= off) x += y;
        }
        if (lane == 31) wsum[wid] = x;
        __syncthreads();
        if (wid == 0) {
            int w = wsum[lane];
#pragma unroll
            for (int off = 1; off < 32; off <<= 1) {
                int y = __shfl_up_sync(0xffffffffu, w, off);
                if (lane >= off) w += y;
            }
            wsum[lane] = w;
        }
        __syncthreads();
        int wpre = (wid > 0) ? wsum[wid - 1] : 0;
        int excl = carry_sh + wpre + x - tsum;
        if (g < NGRP) {
            int run = excl;
#pragma unroll
            for (int j = 0; j < 8; j++) {
                g_off[g * 8 + j]  = run;
                g_fill[g * 8 + j] = run;
                run += v[j];
                ls += logf((float)v[j] + 1.0f);
            }
        }
        __syncthreads();
        if (tid == 1023) carry_sh += wsum[31];
        __syncthreads();
    }
    if (tid == 0) g_off[N_NODES] = N_EDGES;

#pragma unroll
    for (int m = 16; m > 0; m >>= 1) ls += __shfl_xor_sync(0xffffffffu, ls, m);
    if (lane == 0) fred[wid] = ls;
    __syncthreads();
    if (wid == 0) {
        float s = fred[lane];
#pragma unroll
        for (int m = 16; m > 0; m >>= 1) s += __shfl_xor_sync(0xffffffffu, s, m);
        if (lane == 0) ssum_sh = s;
    }
    __syncthreads();
    float inv_mean = (float)N_NODES / ssum_sh;
#pragma unroll 1
    for (int g = tid; g < NGRP; g += 1024) {
        int4 a = *reinterpret_cast<const int4*>(g_deg + g * 8);
        int4 b = *reinterpret_cast<const int4*>(g_deg + g * 8 + 4);
        float4 o0, o1;
        o0.x = logf((float)a.x + 1.0f) * inv_mean;
        o0.y = logf((float)a.y + 1.0f) * inv_mean;
        o0.z = logf((float)a.z + 1.0f) * inv_mean;
        o0.w = logf((float)a.w + 1.0f) * inv_mean;
        o1.x = logf((float)b.x + 1.0f) * inv_mean;
        o1.y = logf((float)b.y + 1.0f) * inv_mean;
        o1.z = logf((float)b.z + 1.0f) * inv_mean;
        o1.w = logf((float)b.w + 1.0f) * inv_mean;
        *reinterpret_cast<float4*>(g_scaleS + g * 8)     = o0;
        *reinterpret_cast<float4*>(g_scaleS + g * 8 + 4) = o1;
    }
}

// merged: CSR fill + zero-deg(for next call) + cvtx + cvtW transpose + cvtrel
__global__ void k_prep(const int* __restrict__ esrc, const int* __restrict__ edst,
                       const int* __restrict__ etype, const float* __restrict__ ew,
                       const float* __restrict__ x0, const float* __restrict__ linw,
                       const float* __restrict__ relw) {
    __shared__ float tile[32][33];
    int b = blockIdx.x;
    int tid = threadIdx.x;

    if (b < PB_ZERO) {                                   // CSR fill
        int e = b * 256 + tid;
        if (e < N_EDGES) {
            int d = edst[e];
            int p = atomicAdd(&g_fill[d], 1);
            g_epk[p] = esrc[e] | (etype[e] << 17);
            g_ew[p]  = ew[e];
        }
    } else if (b < PB_CVTX) {                            // zero deg for next call
        int i = (b - PB_ZERO) * 256 + tid;
        if (i < N_NODES) g_deg[i] = 0;
    } else if (b < PB_CVTW) {                            // x0 -> half chunks 48..51
        int i = (b - PB_CVTX) * 256 + tid;               // exactly N_NODES*32
        int n = i >> 5, g = i & 31;
        int col = g * 4;
        float4 v = __ldg(reinterpret_cast<const float4*>(x0 + n * 128) + g);
        int ch = 48 + (col >> 5);
        int off = col & 31;
        __half2 lo = __floats2half2_rn(v.x, v.y);
        __half2 hi = __floats2half2_rn(v.z, v.w);
        *reinterpret_cast<uint2*>(g_Ah + ((size_t)ch * N_NODES + n) * 32 + off) =
            make_uint2(*reinterpret_cast<uint32_t*>(&lo),
                       *reinterpret_cast<uint32_t*>(&hi));
    } else if (b < PB_CVTR) {                            // W transpose -> half
        int bb = b - PB_CVTW;                            // 832 blocks = 4l * 52k * 4n
        int l = bb / 208;
        int rem = bb % 208;
        int k0 = (rem >> 2) * 32, n0 = (rem & 3) * 32;
        int tx = tid & 31, ty = tid >> 5;
        const float* src = linw + l * KDIM * DIM;
#pragma unroll
        for (int r = 0; r < 4; r++) {
            int k = k0 + ty + r * 8;
            tile[ty + r * 8][tx] = src[k * DIM + n0 + tx];
        }
        __syncthreads();
        __half* dst = g_Wth + l * DIM * KDIM;
#pragma unroll
        for (int r = 0; r < 4; r++) {
            int n = n0 + ty + r * 8;
            dst[n * KDIM + k0 + tx] = __float2half_rn(tile[tx][ty + r * 8]);
        }
    } else {                                             // rel weights -> half
        int i = (b - PB_CVTR) * 256 + tid;
        if (i < 4 * N_REL * DIM) g_relh[i] = __float2half_rn(relw[i]);
    }
}

// ---------------- per-layer aggregation (warp per node, half2 math) --------
__global__ void k_agg(const float* __restrict__ x0, const __half* __restrict__ relh) {
    int gw   = (blockIdx.x * blockDim.x + threadIdx.x) >> 5;
    int lane = threadIdx.x & 31;
    if (gw >= N_NODES) return;
    int beg = g_off[gw], end = g_off[gw + 1];

    float4  vs  = make_float4(0.f, 0.f, 0.f, 0.f);
    float4  vq  = make_float4(0.f, 0.f, 0.f, 0.f);
    __half2 hmx0 = __float2half2_rn(-INFINITY), hmx1 = hmx0;
    __half2 hmn0 = __float2half2_rn( INFINITY), hmn1 = hmn0;

    const __half* xh = g_Ah + ((size_t)(48 + (lane >> 3)) * N_NODES) * 32
                       + 4 * (lane & 7);
    const __half* rh = relh + lane * 4;

    auto edgeAcc = [&](uint2 xu, uint2 ru, float w) {
        __half2 xa = *reinterpret_cast<__half2*>(&xu.x);
        __half2 xb = *reinterpret_cast<__half2*>(&xu.y);
        __half2 ra = *reinterpret_cast<__half2*>(&ru.x);
        __half2 rb = *reinterpret_cast<__half2*>(&ru.y);
        __half2 w2 = __float2half2_rn(w);
        __half2 m0 = __hmul2(__hmul2(xa, ra), w2);
        __half2 m1 = __hmul2(__hmul2(xb, rb), w2);
        hmx0 = __hmax2(hmx0, m0); hmx1 = __hmax2(hmx1, m1);
        hmn0 = __hmin2(hmn0, m0); hmn1 = __hmin2(hmn1, m1);
        float2 f0 = __half22float2(m0), f1 = __half22float2(m1);
        vs.x += f0.x; vs.y += f0.y; vs.z += f1.x; vs.w += f1.y;
        vq.x = fmaf(f0.x, f0.x, vq.x); vq.y = fmaf(f0.y, f0.y, vq.y);
        vq.z = fmaf(f1.x, f1.x, vq.z); vq.w = fmaf(f1.y, f1.y, vq.w);
    };

    int e = beg;
    for (; e + 4 <= end; e += 4) {
        int pk[4]; float w[4]; uint2 xu[4], ru[4];
#pragma unroll
        for (int i = 0; i < 4; i++) {
            pk[i] = __ldg(g_epk + e + i);
            w[i]  = __ldg(g_ew + e + i);
        }
#pragma unroll
        for (int i = 0; i < 4; i++) {
            int s = pk[i] & 0x1FFFF, t = pk[i] >> 17;
            xu[i] = __ldg(reinterpret_cast<const uint2*>(xh + (size_t)s * 32));
            ru[i] = __ldg(reinterpret_cast<const uint2*>(rh + t * 128));
        }
#pragma unroll
        for (int i = 0; i < 4; i++) edgeAcc(xu[i], ru[i], w[i]);
    }
    for (; e < end; e++) {
        int   pk = __ldg(g_epk + e);
        float w  = __ldg(g_ew + e);
        int s = pk & 0x1FFFF, t = pk >> 17;
        uint2 xu = __ldg(reinterpret_cast<const uint2*>(xh + (size_t)s * 32));
        uint2 ru = __ldg(reinterpret_cast<const uint2*>(rh + t * 128));
        edgeAcc(xu, ru, w);
    }

    // convert half minmax to fp32, merge boundary x0 (fp32)
    float2 fx0 = __half22float2(hmx0), fx1 = __half22float2(hmx1);
    float2 fn0 = __half22float2(hmn0), fn1 = __half22float2(hmn1);
    float4 vmx = make_float4(fx0.x, fx0.y, fx1.x, fx1.y);
    float4 vmn = make_float4(fn0.x, fn0.y, fn1.x, fn1.y);

    float4 b = __ldg(reinterpret_cast<const float4*>(x0) + gw * 32 + lane);
    vs.x += b.x; vs.y += b.y; vs.z += b.z; vs.w += b.w;
    vq.x = fmaf(b.x, b.x, vq.x); vq.y = fmaf(b.y, b.y, vq.y);
    vq.z = fmaf(b.z, b.z, vq.z); vq.w = fmaf(b.w, b.w, vq.w);
    vmx.x = fmaxf(vmx.x, b.x); vmx.y = fmaxf(vmx.y, b.y);
    vmx.z = fmaxf(vmx.z, b.z); vmx.w = fmaxf(vmx.w, b.w);
    vmn.x = fminf(vmn.x, b.x); vmn.y = fminf(vmn.y, b.y);
    vmn.z = fminf(vmn.z, b.z); vmn.w = fminf(vmn.w, b.w);

    float dinv = 1.0f / ((float)(end - beg) + 1.0f);
    float4 mean = make_float4(vs.x * dinv, vs.y * dinv, vs.z * dinv, vs.w * dinv);
    float4 sqm  = make_float4(vq.x * dinv, vq.y * dinv, vq.z * dinv, vq.w * dinv);
    float4 stdv;
    stdv.x = sqrtf(fmaxf(sqm.x - mean.x * mean.x, 1e-6f));
    stdv.y = sqrtf(fmaxf(sqm.y - mean.y * mean.y, 1e-6f));
    stdv.z = sqrtf(fmaxf(sqm.z - mean.z * mean.z, 1e-6f));
    stdv.w = sqrtf(fmaxf(sqm.w - mean.w * mean.w, 1e-6f));

    float sS = __ldg(g_scaleS + gw);
    float facs[3] = {1.0f, sS, 1.0f / fmaxf(sS, 1e-2f)};
    int sub = lane >> 3;
    int off = 4 * (lane & 7);

    auto stv = [&](int f, const float4& v) {
#pragma unroll
        for (int j = 0; j < 3; j++) {
            float fac = facs[j];
            __half2 lo = __floats2half2_rn(v.x * fac, v.y * fac);
            __half2 hi = __floats2half2_rn(v.z * fac, v.w * fac);
            int ch = (j * 4 + f) * 4 + sub;
            *reinterpret_cast<uint2*>(g_Ah + ((size_t)ch * N_NODES + gw) * 32 + off) =
                make_uint2(*reinterpret_cast<uint32_t*>(&lo),
                           *reinterpret_cast<uint32_t*>(&hi));
        }
    };
    stv(0, mean); stv(1, vmx); stv(2, vmn); stv(3, stdv);
}

// ---------------- fp16 tensor-core GEMM + LN + ReLU + residual --------------
// 64x128 block tile, 8 warps (2m x 4n), warp tile 32x32, NSTG=4, occ 3.
__global__ void __launch_bounds__(256, 3)
k_gemm(const __half* __restrict__ Wt, const float* __restrict__ bias,
       const float* __restrict__ lng, const float* __restrict__ lnb,
       const float* __restrict__ xin) {
    extern __shared__ __align__(16) char dynsm[];
    __shared__ float redS[64][4];
    __shared__ float redQ[64][4];

    uint32_t smA0 = (uint32_t)__cvta_generic_to_shared(dynsm);
    uint32_t smB0 = smA0 + NSTG * TILEA;

    int tid  = threadIdx.x;
    int lane = tid & 31, wid = tid >> 5;
    int wm = wid & 1, wn = wid >> 1;      // warp grid 2(m) x 4(n)
    int q = lane >> 2, p = lane & 3;
    int lrow = lane & 7;
    int lb3  = (lane >> 3) & 1;
    int lb4  = (lane >> 4) & 1;
    int row0 = blockIdx.x * 64;

    int arow = tid >> 2, aseg = tid & 3;  // A loader: 4 threads/row, 16B each
    int grow = row0 + arow;
    bool rok = grow < N_NODES;
    int brow = tid >> 1, bhf = tid & 1;   // B loader: 2 threads/row, 32B each

    float acc[2][4][4];
#pragma unroll
    for (int i = 0; i < 2; i++)
#pragma unroll
        for (int j = 0; j < 4; j++)
#pragma unroll
            for (int c = 0; c < 4; c++) acc[i][j][c] = 0.0f;

    auto issueTile = [&](int kt) {
        int buf = kt & (NSTG - 1);
        if (rok) {
            const __half* srcA = g_Ah + ((size_t)kt * N_NODES + grow) * 32 + aseg * 8;
            uint32_t dA = smA0 + buf * TILEA + arow * 80 + aseg * 16;
            asm volatile("cp.async.ca.shared.global [%0], [%1], 16;\n"
                         :: "r"(dA), "l"(srcA));
        }
        const __half* srcB = Wt + (size_t)brow * KDIM + kt * BK + bhf * 16;
        uint32_t dB = smB0 + buf * TILEBB + brow * 80 + bhf * 32;
        asm volatile("cp.async.ca.shared.global [%0], [%1], 16;\n"
                     :: "r"(dB), "l"(srcB));
        asm volatile("cp.async.ca.shared.global [%0], [%1], 16;\n"
                     :: "r"(dB + 16), "l"(srcB + 8));
        asm volatile("cp.async.commit_group;\n");
    };

    issueTile(0);
    issueTile(1);
    issueTile(2);

#pragma unroll 1
    for (int kt = 0; kt < NKT; kt++) {
        int buf = kt & (NSTG - 1);
        int ahead = NKT - 1 - kt;
        if (ahead >= 2) {
            asm volatile("cp.async.wait_group 2;\n");
        } else if (ahead == 1) {
            asm volatile("cp.async.wait_group 1;\n");
        } else {
            asm volatile("cp.async.wait_group 0;\n");
        }
        __syncthreads();
        if (kt + 3 < NKT) issueTile(kt + 3);

        uint32_t Abase = smA0 + buf * TILEA;
        uint32_t Bbase = smB0 + buf * TILEBB;

#pragma unroll
        for (int kk = 0; kk < 2; kk++) {
            uint32_t a[2][4], b[2][4];
#pragma unroll
            for (int mt = 0; mt < 2; mt++) {
                int ar = wm * 32 + mt * 16 + lrow + lb3 * 8;
                int ac = kk * 16 + lb4 * 8;
                uint32_t addr = Abase + ar * 80 + ac * 2;
                asm volatile(
                    "ldmatrix.sync.aligned.m8n8.x4.shared.b16 {%0,%1,%2,%3}, [%4];"
                    : "=r"(a[mt][0]), "=r"(a[mt][1]), "=r"(a[mt][2]), "=r"(a[mt][3])
                    : "r"(addr));
            }
#pragma unroll
            for (int ntp = 0; ntp < 2; ntp++) {
                int br = wn * 32 + ntp * 16 + lrow + lb4 * 8;
                int bc = kk * 16 + lb3 * 8;
                uint32_t addr = Bbase + br * 80 + bc * 2;
                asm volatile(
                    "ldmatrix.sync.aligned.m8n8.x4.shared.b16 {%0,%1,%2,%3}, [%4];"
                    : "=r"(b[ntp][0]), "=r"(b[ntp][1]), "=r"(b[ntp][2]), "=r"(b[ntp][3])
                    : "r"(addr));
            }
#pragma unroll
            for (int mt = 0; mt < 2; mt++)
#pragma unroll
                for (int nt = 0; nt < 4; nt++) {
                    int ntp = nt >> 1, hh = (nt & 1) * 2;
                    asm volatile(
                        "mma.sync.aligned.m16n8k16.row.col.f32.f16.f16.f32 "
                        "{%0,%1,%2,%3}, {%4,%5,%6,%7}, {%8,%9}, {%0,%1,%2,%3};"
                        : "+f"(acc[mt][nt][0]), "+f"(acc[mt][nt][1]),
                          "+f"(acc[mt][nt][2]), "+f"(acc[mt][nt][3])
                        : "r"(a[mt][0]), "r"(a[mt][1]), "r"(a[mt][2]), "r"(a[mt][3]),
                          "r"(b[ntp][hh]), "r"(b[ntp][hh + 1]));
                }
        }
    }
    __syncthreads();

    // ---- epilogue: bias + LN + ReLU + residual (+ half x chunks) ----
    float2 bias2[4], lng2[4], lnb2[4];
#pragma unroll
    for (int nt = 0; nt < 4; nt++) {
        int c = wn * 32 + nt * 8 + 2 * p;
        bias2[nt] = *reinterpret_cast<const float2*>(bias + c);
        lng2[nt]  = *reinterpret_cast<const float2*>(lng + c);
        lnb2[nt]  = *reinterpret_cast<const float2*>(lnb + c);
    }

#pragma unroll
    for (int mt = 0; mt < 2; mt++) {
        float sA = 0.f, qA = 0.f, sB = 0.f, qB = 0.f;
#pragma unroll
        for (int nt = 0; nt < 4; nt++) {
            float v0 = acc[mt][nt][0] + bias2[nt].x;
            float v1 = acc[mt][nt][1] + bias2[nt].y;
            float v2 = acc[mt][nt][2] + bias2[nt].x;
            float v3 = acc[mt][nt][3] + bias2[nt].y;
            sA += v0 + v1; qA += v0 * v0 + v1 * v1;
            sB += v2 + v3; qB += v2 * v2 + v3 * v3;
        }
#pragma unroll
        for (int m = 1; m < 4; m <<= 1) {
            sA += __shfl_xor_sync(0xffffffffu, sA, m);
            qA += __shfl_xor_sync(0xffffffffu, qA, m);
            sB += __shfl_xor_sync(0xffffffffu, sB, m);
            qB += __shfl_xor_sync(0xffffffffu, qB, m);
        }
        if (p == 0) {
            int rA = wm * 32 + mt * 16 + q;
            redS[rA][wn] = sA; redQ[rA][wn] = qA;
            redS[rA + 8][wn] = sB; redQ[rA + 8][wn] = qB;
        }
    }
    __syncthreads();

#pragma unroll
    for (int mt = 0; mt < 2; mt++) {
#pragma unroll
        for (int half = 0; half < 2; half++) {
            int rloc = wm * 32 + mt * 16 + q + half * 8;
            int r = row0 + rloc;
            float s = redS[rloc][0] + redS[rloc][1] + redS[rloc][2] + redS[rloc][3];
            float sq = redQ[rloc][0] + redQ[rloc][1] + redQ[rloc][2] + redQ[rloc][3];
            float mu = s * (1.0f / 128.0f);
            float var = sq * (1.0f / 128.0f) - mu * mu;
            float rstd = rsqrtf(var + 1e-5f);
            if (r < N_NODES) {
#pragma unroll
                for (int nt = 0; nt < 4; nt++) {
                    int c = wn * 32 + nt * 8 + 2 * p;
                    float v0 = acc[mt][nt][half * 2 + 0] + bias2[nt].x;
                    float v1 = acc[mt][nt][half * 2 + 1] + bias2[nt].y;
                    float o0 = fmaxf((v0 - mu) * rstd * lng2[nt].x + lnb2[nt].x, 0.0f);
                    float o1 = fmaxf((v1 - mu) * rstd * lng2[nt].y + lnb2[nt].y, 0.0f);
                    float2 xr = *reinterpret_cast<const float2*>(xin + r * 128 + c);
                    float n0 = o0 + xr.x, n1 = o1 + xr.y;
                    *reinterpret_cast<float2*>(g_x + r * 128 + c) = make_float2(n0, n1);
                    __half2 hx = __floats2half2_rn(n0, n1);
                    *reinterpret_cast<uint32_t*>(
                        g_Ah + ((size_t)(48 + wn) * N_NODES + r) * 32 + nt * 8 + 2 * p) =
                        *reinterpret_cast<uint32_t*>(&hx);
                }
            }
        }
    }
}

// ---------------- distmult scoring (warp per triple) ------------------------
__global__ void k_score(const int* __restrict__ src, const int* __restrict__ rel,
                        const int* __restrict__ dst, const float* __restrict__ qw,
                        float* __restrict__ out) {
    int gw   = (blockIdx.x * blockDim.x + threadIdx.x) >> 5;
    int lane = threadIdx.x & 31;
    if (gw >= 1024 * 32) return;
    int s = __ldg(src + gw), r = __ldg(rel + gw), d = __ldg(dst + gw);
    const float4* xv = reinterpret_cast<const float4*>(g_x);
    float4 a = __ldg(xv + s * 32 + lane);
    float4 qq = __ldg(reinterpret_cast<const float4*>(qw) + r * 32 + lane);
    float4 c = __ldg(xv + d * 32 + lane);
    float pr = a.x * qq.x * c.x + a.y * qq.y * c.y + a.z * qq.z * c.z + a.w * qq.w * c.w;
#pragma unroll
    for (int m = 16; m > 0; m >>= 1) pr += __shfl_xor_sync(0xffffffffu, pr, m);
    if (lane == 0) out[gw] = pr;
}

// ---------------- launcher ---------------------------------------------------
extern "C" void kernel_launch(void* const* d_in, const int* in_sizes, int n_in,
                              void* d_out, int out_size) {
    const float* x0    = (const float*)d_in[0];
    const int*   eidx  = (const int*)  d_in[1];
    const int*   etype = (const int*)  d_in[2];
    const float* ew    = (const float*)d_in[3];
    const float* relw  = (const float*)d_in[4];
    const float* linw  = (const float*)d_in[5];
    const float* linb  = (const float*)d_in[6];
    const float* lng   = (const float*)d_in[7];
    const float* lnb   = (const float*)d_in[8];
    const float* qw    = (const float*)d_in[9];
    const int*   src   = (const int*)  d_in[10];
    const int*   rel   = (const int*)  d_in[11];
    const int*   dst   = (const int*)  d_in[12];
    float*       out   = (float*)d_out;

    const int* esrc = eidx;
    const int* edst = eidx + N_EDGES;

    float*  gx;   cudaGetSymbolAddress((void**)&gx, g_x);
    __half* gWh;  cudaGetSymbolAddress((void**)&gWh, g_Wth);
    __half* grh;  cudaGetSymbolAddress((void**)&grh, g_relh);

    static int attr_set = 0;
    if (!attr_set) {
        cudaFuncSetAttribute(k_gemm, cudaFuncAttributeMaxDynamicSharedMemorySize,
                             NSTG * (TILEA + TILEBB));
        attr_set = 1;
    }

    // g_deg is zero-initialized at load; k_prep re-zeroes it each call after use.
    k_hist<<<(N_EDGES + 255) / 256, 256>>>(edst);                       // 0
    k_scan<<<1, 1024>>>();                                              // 1
    k_prep<<<PB_TOT, 256>>>(esrc, edst, etype, ew, x0, linw, relw);     // 2

    for (int l = 0; l < 4; l++) {
        const float* xin = (l == 0) ? x0 : gx;
        k_agg<<<(N_NODES * 32 + 255) / 256, 256>>>(x0, grh + l * N_REL * DIM);  // 3
        k_gemm<<<(N_NODES + 63) / 64, 256, NSTG * (TILEA + TILEBB)>>>(          // 4 <- ncu
            gWh + (size_t)l * DIM * KDIM,
            linb + l * DIM,
            lng + l * DIM,
            lnb + l * DIM,
            xin);
    }

    k_score<<<(1024 * 32 * 32 + 255) / 256, 256>>>(src, rel, dst, qw, out);
}